// round 16
// baseline (speedup 1.0000x reference)
#include <cuda_runtime.h>
#include <cuda_fp16.h>
#include <cstdint>

// ConvNearestNeightbor: out[b, n*C+c, h, w] = max_k |x_pad[b,c,h-row,w-col] - nb[n,c,k]|
// R16: R12's pipe-balanced fp16 body at <=36 regs so 7 blocks/SM co-reside:
// 1024 blocks x 8 warps = 8192 warps = 55/SM in ONE wave (R12's 39 regs -> 6/SM ->
// 888+136 two-wave split). Register diet: running max chains (live temps 9 -> 2),
// neighbors kept packed in uint4. launch_bounds(256, 7).

namespace {

constexpr int B = 16, C = 32, H = 32, W = 32, NUM = 32;
constexpr int HW = H * W;
constexpr int NSPLIT = 2;
constexpr int NPER = NUM / NSPLIT;  // 16

__device__ __forceinline__ uint32_t h2bits(__half2 v) { return *reinterpret_cast<uint32_t*>(&v); }
__device__ __forceinline__ __half2 bits2h(uint32_t v) { return *reinterpret_cast<__half2*>(&v); }
// |x - n| bits: HSUB2 (fma) + LOP3 sign-clear (alu)
__device__ __forceinline__ uint32_t absdiff(uint32_t xv, uint32_t nk) {
  __half2 d = __hsub2(bits2h(xv), bits2h(nk));
  return h2bits(d) & 0x7FFF7FFFu;
}
__device__ __forceinline__ uint32_t umax2(uint32_t a, uint32_t b) {
  uint32_t r;
  asm("max.u16x2 %0, %1, %2;" : "=r"(r) : "r"(a), "r"(b));
  return r;
}
__device__ __forceinline__ uint32_t hmax2b(uint32_t a, uint32_t b) {
  __half2 r = __hmax2(bits2h(a), bits2h(b));
  return h2bits(r);
}

__global__ __launch_bounds__(256, 7) void cnn_kernel(
    const float* __restrict__ x,
    const float* __restrict__ nb,
    float* __restrict__ out) {
  __shared__ __align__(16) __half xs[34 * 36];     // fp16 halo tile
  __shared__ __align__(16) __half2 nbs[NPER][16];  // duplicated {n,n}, padded rows

  const int bc = blockIdx.x;   // 0 .. B*C-1
  const int ns = blockIdx.y;   // 0 .. NSPLIT-1
  const int c  = bc & (C - 1);
  const int b  = bc / C;
  const int tid = threadIdx.x;

  const int h  = tid >> 3;          // 0..31
  const int wq = (tid & 7) << 2;    // 0,4,...,28

  // ---- neighbors first; duplicated into half2 ----
  if (tid < NPER * 9) {
    int nn = tid / 9;
    int k  = tid - nn * 9;
    float v = nb[(size_t)(ns * NPER + nn) * (C * 9) + c * 9 + k];
    nbs[nn][k] = __float2half2_rn(v);
  }

  // ---- x tile: 1 vector LDG per thread -> fp16, + predicated halo zeros ----
  const float* xp = x + (size_t)bc * HW;
  {
    float4 v = *(const float4*)(xp + h * W + wq);
    __half* dst = &xs[(h + 1) * 36 + wq + 1];
    dst[0] = __float2half_rn(v.x);
    dst[1] = __float2half_rn(v.y);
    dst[2] = __float2half_rn(v.z);
    dst[3] = __float2half_rn(v.w);
  }
  if (tid < 132) {  // halo: rows 0,33 cols 0..33; cols 0,33 rows 1..32
    int rr, cc;
    if (tid < 68)        { rr = (tid < 34) ? 0 : 33; cc = (tid < 34) ? tid : tid - 34; }
    else if (tid < 100)  { rr = tid - 68 + 1;  cc = 0; }
    else                 { rr = tid - 100 + 1; cc = 33; }
    *(unsigned short*)&xs[rr * 36 + cc] = 0;
  }
  __syncthreads();

  // ---- window: 5 sliding half2 pairs per row ----
  uint32_t pr[3][5];
#pragma unroll
  for (int r = 0; r < 3; r++) {
    const __half* base = &xs[(h + r) * 36 + wq];   // 8B-aligned
    uint2 v01 = *(const uint2*)base;
    uint32_t v45 = *(const uint32_t*)(base + 4);
    pr[r][0] = v01.x;
    pr[r][2] = v01.y;
    pr[r][4] = v45;
    __half2 s1 = __halves2half2(__high2half(bits2h(v01.x)), __low2half(bits2h(v01.y)));
    __half2 s3 = __halves2half2(__high2half(bits2h(v01.y)), __low2half(bits2h(v45)));
    pr[r][1] = h2bits(s1);
    pr[r][3] = h2bits(s3);
  }

  float* const outp =
      out + ((size_t)(b * NUM + ns * NPER) * C + c) * HW + h * W + wq;

#pragma unroll 4
  for (int nn = 0; nn < NPER; nn++) {
    // neighbors kept packed: 2 uint4 + 1 scalar (11 regs, no unpacked array)
    const uint4 c0 = *(const uint4*)&nbs[nn][0];   // k0..k3
    const uint4 c1 = *(const uint4*)&nbs[nn][4];   // k4..k7
    const uint32_t n8 = h2bits(nbs[nn][8]);

    uint32_t m[2];
#pragma unroll
    for (int p = 0; p < 2; p++) {
      const int q = 2 * p;
      // tap k -> r = 2-k/3, cc = 2-k%3 ; x-pair = pr[r][cc+q]
      // fma-pipe running chain over taps 0..3 (HMNMX), live temps: 1
      uint32_t mh = hmax2b(absdiff(pr[2][2 + q], c0.x),
                           absdiff(pr[2][1 + q], c0.y));
      mh = hmax2b(mh, absdiff(pr[2][0 + q], c0.z));
      mh = hmax2b(mh, absdiff(pr[1][2 + q], c0.w));
      // alu-pipe running chain over taps 4..8 (VIMNMX)
      uint32_t mu = umax2(absdiff(pr[1][1 + q], c1.x),
                          absdiff(pr[1][0 + q], c1.y));
      mu = umax2(mu, absdiff(pr[0][2 + q], c1.z));
      mu = umax2(mu, absdiff(pr[0][1 + q], c1.w));
      mu = umax2(mu, absdiff(pr[0][0 + q], n8));
      m[p] = umax2(mu, mh);
    }

    float2 f01 = __half22float2(bits2h(m[0]));
    float2 f23 = __half22float2(bits2h(m[1]));
    *(float4*)(outp + (size_t)nn * C * HW) =
        make_float4(f01.x, f01.y, f23.x, f23.y);
  }
}

}  // namespace

extern "C" void kernel_launch(void* const* d_in, const int* in_sizes, int n_in,
                              void* d_out, int out_size) {
  const float* x  = (const float*)d_in[0];   // (B,C,H,W) fp32
  const float* nb = (const float*)d_in[1];   // (NUM,C,9) fp32
  float* out = (float*)d_out;                // (B, NUM*C, H, W) fp32
  dim3 grid(B * C, NSPLIT);
  cnn_kernel<<<grid, 256>>>(x, nb, out);
}